// round 15
// baseline (speedup 1.0000x reference)
#include <cuda_runtime.h>
#include <cuda_fp16.h>
#include <math.h>
#include <stdint.h>

// ---------------- problem constants ----------------
#define SEQ     2048
#define DMODEL  512
#define DINNER  1024
#define DSTATE  64
#define DTRANK  32
#define DCONV   4
#define XZCOLS  (2*DINNER)          // 2048
#define DBCCOLS (DTRANK + 2*DSTATE) // 160
#define NSPLIT  4
#define G4SPLIT 4
#define NC      8                   // scan chunks
#define LC      (SEQ/NC)            // 256 timesteps per chunk

// ---------------- scratch (device globals; no allocation) ----------------
__device__ float g_xz    [SEQ*XZCOLS];
__device__ float g_xiT   [DINNER*SEQ];
__device__ float g_zsT   [DINNER*SEQ];
__device__ float g_dbcp  [NSPLIT*SEQ*DBCCOLS];
__device__ float g_dbc   [SEQ*DBCCOLS];
__device__ float g_dT    [DINNER*SEQ];
__device__ float g_S     [DINNER*NC];
__device__ float g_hend  [NC*DINNER*DSTATE];
__device__ float g_hstart[NC*DINNER*DSTATE];
__device__ float g_outp  [G4SPLIT*SEQ*DMODEL];   // G4 split-K partials

// fp16 operand buffers
__device__ __align__(16) __half g_xnh  [SEQ*DMODEL];
__device__ __align__(16) __half g_xnl  [SEQ*DMODEL];
__device__ __align__(16) __half g_Winh [XZCOLS*DMODEL];
__device__ __align__(16) __half g_xih  [SEQ*DINNER];
__device__ __align__(16) __half g_xil  [SEQ*DINNER];
__device__ __align__(16) __half g_Wxh  [DBCCOLS*DINNER];
__device__ __align__(16) __half g_dth  [SEQ*DTRANK];
__device__ __align__(16) __half g_Wdth [DINNER*DTRANK];
__device__ __align__(16) __half g_Wdtl [DINNER*DTRANK];
__device__ __align__(16) __half g_yh   [SEQ*DINNER];
__device__ __align__(16) __half g_yl   [SEQ*DINNER];
__device__ __align__(16) __half g_Wouth[DMODEL*DINNER];

// ---------------- helpers ----------------
__device__ __forceinline__ float siluf(float x) { return x / (1.0f + __expf(-x)); }
__device__ __forceinline__ float softplusf(float x) {
    return (x > 15.0f) ? x : log1pf(__expf(x));
}
__device__ __forceinline__ uint32_t smem_u32(const void* p) {
    uint32_t a;
    asm("{ .reg .u64 t; cvta.to.shared.u64 t, %1; cvt.u32.u64 %0, t; }"
        : "=r"(a) : "l"(p));
    return a;
}
__device__ __forceinline__ void ldsm4(uint32_t& r0, uint32_t& r1,
                                      uint32_t& r2, uint32_t& r3, uint32_t addr) {
    asm volatile("ldmatrix.sync.aligned.m8n8.x4.shared.b16 {%0,%1,%2,%3}, [%4];"
                 : "=r"(r0), "=r"(r1), "=r"(r2), "=r"(r3) : "r"(addr));
}
__device__ __forceinline__ void mma_f16(float* c, uint32_t a0, uint32_t a1,
                                        uint32_t a2, uint32_t a3,
                                        uint32_t b0, uint32_t b1) {
    asm volatile(
        "mma.sync.aligned.m16n8k16.row.col.f32.f16.f16.f32 "
        "{%0,%1,%2,%3}, {%4,%5,%6,%7}, {%8,%9}, {%0,%1,%2,%3};"
        : "+f"(c[0]), "+f"(c[1]), "+f"(c[2]), "+f"(c[3])
        : "r"(a0), "r"(a1), "r"(a2), "r"(a3), "r"(b0), "r"(b1));
}
__device__ __forceinline__ uint32_t hpack2(float x, float y) {
    __half2 h = __floats2half2_rn(x, y);
    return *(uint32_t*)&h;
}
__device__ __forceinline__ void splitH2(float x, float y,
                                        uint32_t& hi, uint32_t& lo) {
    __half2 h = __floats2half2_rn(x, y);
    __half2 l = __floats2half2_rn(x - __low2float(h), y - __high2float(h));
    hi = *(uint32_t*)&h;
    lo = *(uint32_t*)&l;
}

// ---------------- fused weight split (one launch) ----------------
__global__ void split_all_kernel(const float* __restrict__ Win,
                                 const float* __restrict__ Wx,
                                 const float* __restrict__ Wdt,
                                 const float* __restrict__ Wout)
{
    int b = blockIdx.x;
    if (b < 1184 || b >= 1216) {
        const float* src;
        __half* hi;
        int off;
        if (b < 1024)      { src = Win;  hi = g_Winh;  off = b; }
        else if (b < 1184) { src = Wx;   hi = g_Wxh;   off = b - 1024; }
        else               { src = Wout; hi = g_Wouth; off = b - 1216; }
        int i = (off * 256 + threadIdx.x) * 4;
        float4 v = *(const float4*)&src[i];
        *(uint2*)&hi[i] = make_uint2(hpack2(v.x, v.y), hpack2(v.z, v.w));
    } else {
        int off = b - 1184;
        int i = (off * 256 + threadIdx.x) * 4;
        float4 v = *(const float4*)&Wdt[i];
        uint32_t h0, l0, h1, l1;
        splitH2(v.x, v.y, h0, l0);
        splitH2(v.z, v.w, h1, l1);
        *(uint2*)&g_Wdth[i] = make_uint2(h0, h1);
        *(uint2*)&g_Wdtl[i] = make_uint2(l0, l1);
    }
}

// ---------------- LayerNorm: one block per token, emits fp16 hi/lo ----------------
__global__ void ln_kernel(const float* __restrict__ x,
                          const float* __restrict__ g,
                          const float* __restrict__ b)
{
    int t   = blockIdx.x;
    int tid = threadIdx.x;
    const float* xr = x + t * DMODEL;
    float2 v = *(const float2*)&xr[tid * 2];
    float s = v.x + v.y;
    float q = v.x * v.x + v.y * v.y;
    #pragma unroll
    for (int o = 16; o > 0; o >>= 1) {
        s += __shfl_xor_sync(0xffffffffu, s, o);
        q += __shfl_xor_sync(0xffffffffu, q, o);
    }
    __shared__ float ss[8], qq[8];
    int lane = tid & 31, w = tid >> 5;
    if (lane == 0) { ss[w] = s; qq[w] = q; }
    __syncthreads();
    s = 0.f; q = 0.f;
    #pragma unroll
    for (int i = 0; i < 8; i++) { s += ss[i]; q += qq[i]; }
    float mu  = s * (1.0f / DMODEL);
    float var = q * (1.0f / DMODEL) - mu * mu;
    float r   = rsqrtf(var + 1e-5f);
    float2 gg = *(const float2*)&g[tid * 2];
    float2 bb = *(const float2*)&b[tid * 2];
    float ox = (v.x - mu) * r * gg.x + bb.x;
    float oy = (v.y - mu) * r * gg.y + bb.y;
    uint32_t h, l;
    splitH2(ox, oy, h, l);
    *(uint32_t*)&g_xnh[t * DMODEL + tid * 2] = h;
    *(uint32_t*)&g_xnl[t * DMODEL + tid * 2] = l;
}

// ---------------- fp16 split HMMA GEMM ----------------
// C[m][n] = sum_k A[m][k]*B[n][k]; A fp16 hi (+lo), B fp16 hi.
// D = Ahi*Bhi + Alo*Bhi. ZSPLIT: blocks with bn >= N/2 skip the Alo pass
// (1-pass fp16; used for the silu-gate columns of G1).
// 32 fp32-k per tile; rows padded to 40 halves. 8 warps 2(m) x 4(n).
// split-K via blockIdx.z. EPI: 0 none, 2 softplus(acc+ep[row]). NGUARD vs N.
template<int BM, int BN, int EPI, bool NGUARD, bool ZSPLIT>
__global__ __launch_bounds__(256, 2)
void mma_gemm(const __half* __restrict__ Ah,
              const __half* __restrict__ Al, int lda,
              const __half* __restrict__ Bh, int ldb,
              float* __restrict__ C, int ldc,
              int M, int N, int K, const float* __restrict__ ep)
{
    constexpr int S = 40;
    constexpr int MT = (BM / 2) / 16;
    constexpr int NT = (BN / 4) / 8;
    constexpr int AIT = BM / 64;
    constexpr int BIT = BN / 64;
    constexpr int PERBUF = (2 * BM + BN) * S;

    extern __shared__ __align__(16) __half sm[];
    const uint32_t sb = smem_u32(sm);

    const int tid = threadIdx.x, lane = tid & 31, wid = tid >> 5;
    const int bm = blockIdx.y * BM, bn = blockIdx.x * BN;
    const int z = blockIdx.z;
    const int kbeg = z * K;
    C += (size_t)z * M * ldc;
    const int wm0 = (wid & 1) * (BM / 2);
    const int wn0 = (wid >> 1) * (BN / 4);
    const bool dop2 = !ZSPLIT || (bn < (N >> 1));   // block-uniform

    const int lA_r = lane & 15;
    const int lA_c = (lane >> 4) << 3;
    const int lB_r = (lane & 7) + ((lane >> 4) << 3);
    const int lB_c = ((lane >> 3) & 1) << 3;

    float acc[MT][NT][4];
    #pragma unroll
    for (int i = 0; i < MT; i++)
        #pragma unroll
        for (int j = 0; j < NT; j++)
            #pragma unroll
            for (int q = 0; q < 4; q++) acc[i][j][q] = 0.0f;

    uint4 vah[AIT], val[AIT], vbh[BIT];

    auto loadG = [&](int k0) {
        #pragma unroll
        for (int i = 0; i < AIT; i++) {
            int idx = tid + i * 256;
            int r = idx >> 2, ch = (idx & 3) << 3;
            size_t s = (size_t)(bm + r) * lda + k0 + ch;
            vah[i] = *(const uint4*)&Ah[s];
            if (dop2) val[i] = *(const uint4*)&Al[s];
        }
        #pragma unroll
        for (int i = 0; i < BIT; i++) {
            int idx = tid + i * 256;
            int r = idx >> 2, ch = (idx & 3) << 3;
            int rr = bn + r;
            if (NGUARD) rr = min(rr, N - 1);
            size_t s = (size_t)rr * ldb + k0 + ch;
            vbh[i] = *(const uint4*)&Bh[s];
        }
    };
    auto storeS = [&](int buf) {
        const int oAh = buf * PERBUF;
        const int oAl = oAh + BM * S;
        const int oBh = oAh + 2 * BM * S;
        #pragma unroll
        for (int i = 0; i < AIT; i++) {
            int idx = tid + i * 256;
            int r = idx >> 2, ch = (idx & 3) << 3;
            *(uint4*)&sm[oAh + r * S + ch] = vah[i];
            if (dop2) *(uint4*)&sm[oAl + r * S + ch] = val[i];
        }
        #pragma unroll
        for (int i = 0; i < BIT; i++) {
            int idx = tid + i * 256;
            int r = idx >> 2, ch = (idx & 3) << 3;
            *(uint4*)&sm[oBh + r * S + ch] = vbh[i];
        }
    };
    auto compute = [&](int buf) {
        const int oAh = buf * PERBUF;
        const int oAl = oAh + BM * S;
        const int oBh = oAh + 2 * BM * S;
        #pragma unroll
        for (int kk = 0; kk < 32; kk += 16) {
            uint32_t af[MT][4];
            uint32_t bh[NT / 2][4];
            #pragma unroll
            for (int mi = 0; mi < MT; mi++) {
                uint32_t addr = sb + (uint32_t)(oAh +
                    (wm0 + mi * 16 + lA_r) * S + kk + lA_c) * 2;
                ldsm4(af[mi][0], af[mi][1], af[mi][2], af[mi][3], addr);
            }
            #pragma unroll
            for (int nj = 0; nj < NT / 2; nj++) {
                uint32_t addr = sb + (uint32_t)(oBh +
                    (wn0 + nj * 16 + lB_r) * S + kk + lB_c) * 2;
                ldsm4(bh[nj][0], bh[nj][1], bh[nj][2], bh[nj][3], addr);
            }
            #pragma unroll
            for (int mi = 0; mi < MT; mi++)
                #pragma unroll
                for (int ni = 0; ni < NT; ni++)
                    mma_f16(acc[mi][ni],
                            af[mi][0], af[mi][1], af[mi][2], af[mi][3],
                            bh[ni >> 1][(ni & 1) * 2],
                            bh[ni >> 1][(ni & 1) * 2 + 1]);
            if (dop2) {
                #pragma unroll
                for (int mi = 0; mi < MT; mi++) {
                    uint32_t addr = sb + (uint32_t)(oAl +
                        (wm0 + mi * 16 + lA_r) * S + kk + lA_c) * 2;
                    ldsm4(af[mi][0], af[mi][1], af[mi][2], af[mi][3], addr);
                }
                #pragma unroll
                for (int mi = 0; mi < MT; mi++)
                    #pragma unroll
                    for (int ni = 0; ni < NT; ni++)
                        mma_f16(acc[mi][ni],
                                af[mi][0], af[mi][1], af[mi][2], af[mi][3],
                                bh[ni >> 1][(ni & 1) * 2],
                                bh[ni >> 1][(ni & 1) * 2 + 1]);
            }
        }
    };

    loadG(kbeg);
    storeS(0);
    __syncthreads();
    int cur = 0;
    const int KT = K / 32;
    for (int kt = 0; kt < KT; kt++) {
        bool has = (kt + 1) < KT;
        if (has) loadG(kbeg + (kt + 1) * 32);
        compute(cur);
        if (has) {
            storeS(cur ^ 1);
            __syncthreads();
            cur ^= 1;
        }
    }

    #pragma unroll
    for (int mi = 0; mi < MT; mi++) {
        #pragma unroll
        for (int ni = 0; ni < NT; ni++) {
            int colb = bn + wn0 + ni * 8;
            if (NGUARD && colb >= N) continue;
            int row = bm + wm0 + mi * 16 + (lane >> 2);
            int col = colb + (lane & 3) * 2;
            float2 v0 = make_float2(acc[mi][ni][0], acc[mi][ni][1]);
            float2 v1 = make_float2(acc[mi][ni][2], acc[mi][ni][3]);
            if (EPI == 2) {
                float b0 = ep[row], b1 = ep[row + 8];
                v0.x = softplusf(v0.x + b0); v0.y = softplusf(v0.y + b0);
                v1.x = softplusf(v1.x + b1); v1.y = softplusf(v1.y + b1);
            }
            *(float2*)&C[(size_t)row * ldc + col] = v0;
            *(float2*)&C[(size_t)(row + 8) * ldc + col] = v1;
        }
    }
}

// reduce the 4 split-K partials (dbc) + fused dt fp16-hi emit
__global__ void reduce4_kernel()
{
    int i = (blockIdx.x * 256 + threadIdx.x) * 4;
    const int TOT = SEQ * DBCCOLS;
    float4 a = *(const float4*)&g_dbcp[0 * TOT + i];
    float4 b = *(const float4*)&g_dbcp[1 * TOT + i];
    float4 c = *(const float4*)&g_dbcp[2 * TOT + i];
    float4 d = *(const float4*)&g_dbcp[3 * TOT + i];
    float4 o;
    o.x = (a.x + b.x) + (c.x + d.x);
    o.y = (a.y + b.y) + (c.y + d.y);
    o.z = (a.z + b.z) + (c.z + d.z);
    o.w = (a.w + b.w) + (c.w + d.w);
    *(float4*)&g_dbc[i] = o;
    int t = i / DBCCOLS, cc = i % DBCCOLS;
    if (cc < DTRANK) {
        *(uint2*)&g_dth[t * DTRANK + cc] =
            make_uint2(hpack2(o.x, o.y), hpack2(o.z, o.w));
    }
}

// reduce 4 split-K partials of G4 and add residual -> final out
__global__ void reduce4_resid_kernel(const float* __restrict__ x,
                                     float* __restrict__ out)
{
    int i = (blockIdx.x * 256 + threadIdx.x) * 4;
    const int TOT = SEQ * DMODEL;
    float4 a = *(const float4*)&g_outp[0 * TOT + i];
    float4 b = *(const float4*)&g_outp[1 * TOT + i];
    float4 c = *(const float4*)&g_outp[2 * TOT + i];
    float4 d = *(const float4*)&g_outp[3 * TOT + i];
    float4 r = *(const float4*)&x[i];
    float4 o;
    o.x = (a.x + b.x) + (c.x + d.x) + r.x;
    o.y = (a.y + b.y) + (c.y + d.y) + r.y;
    o.z = (a.z + b.z) + (c.z + d.z) + r.z;
    o.w = (a.w + b.w) + (c.w + d.w) + r.w;
    *(float4*)&out[i] = o;
}

// ---------------- depthwise conv + silu: emits xi hi/lo (fp16), xiT, zsT ----------------
__global__ __launch_bounds__(256)
void conv_kernel(const float* __restrict__ cw, const float* __restrict__ cb)
{
    __shared__ float sxz[35][33];
    __shared__ float sxi[32][33];
    __shared__ float szs[32][33];
    int t0 = blockIdx.x * 32, c0 = blockIdx.y * 32;
    int tid = threadIdx.x;

    for (int i = tid; i < 35 * 32; i += 256) {
        int r = i >> 5, c = i & 31;
        int gt = t0 + r - 3;
        sxz[r][c] = (gt >= 0) ? g_xz[gt * XZCOLS + c0 + c] : 0.0f;
    }
    for (int i = tid; i < 32 * 32; i += 256) {
        int r = i >> 5, c = i & 31;
        float z = g_xz[(t0 + r) * XZCOLS + DINNER + c0 + c];
        szs[r][c] = siluf(z);
    }
    __syncthreads();

    int cl = tid & 31, tq = tid >> 5;
    float4 w = *(const float4*)&cw[(c0 + cl) * 4];
    float bb = cb[c0 + cl];
    #pragma unroll
    for (int s = 0; s < 4; s++) {
        int tl = tq + s * 8;
        float v = sxz[tl + 0][cl] * w.x + sxz[tl + 1][cl] * w.y +
                  sxz[tl + 2][cl] * w.z + sxz[tl + 3][cl] * w.w + bb;
        v = siluf(v);
        __half h = __float2half_rn(v);
        __half l = __float2half_rn(v - __half2float(h));
        g_xih[(size_t)(t0 + tl) * DINNER + c0 + cl] = h;
        g_xil[(size_t)(t0 + tl) * DINNER + c0 + cl] = l;
        sxi[tl][cl] = v;
    }
    __syncthreads();

    int tl2 = tid & 31, cq = tid >> 5;
    #pragma unroll
    for (int s = 0; s < 4; s++) {
        int cl2 = cq + s * 8;
        g_xiT[(size_t)(c0 + cl2) * SEQ + t0 + tl2] = sxi[tl2][cl2];
        g_zsT[(size_t)(c0 + cl2) * SEQ + t0 + tl2] = szs[tl2][cl2];
    }
}

// ---------------- chunked scan, pass 1 (chunks 0..NC-2 only) ----------------
__global__ __launch_bounds__(256)
void scan_pass1(const float* __restrict__ A_log)
{
    __shared__ __align__(16) float sB[32][68];
    const unsigned FULL = 0xffffffffu;
    int tid = threadIdx.x, lane = tid & 31, w = tid >> 5;
    int d = blockIdx.x * 8 + w;
    int c = blockIdx.y;

    float A0  = -expf(A_log[d * DSTATE + lane]);
    float A1  = -expf(A_log[d * DSTATE + 32 + lane]);
    float d32 = A1 - A0;
    bool uni  = __all_sync(FULL, __shfl_sync(FULL, d32, 0) == d32);
    float h0 = 0.f, h1 = 0.f, ssum = 0.f;

    const float* xT  = g_xiT + (size_t)d * SEQ;
    const float* dTp = g_dT  + (size_t)d * SEQ;
    const int tbeg = c * LC;

    for (int t0 = tbeg; t0 < tbeg + LC; t0 += 32) {
        __syncthreads();
        for (int i = tid; i < 32 * 16; i += 256) {
            int r = i >> 4, q = (i & 15) << 2;
            *(float4*)&sB[r][q] =
                *(const float4*)&g_dbc[(size_t)(t0 + r) * DBCCOLS + 32 + q];
        }
        __syncthreads();

        float myD   = dTp[t0 + lane];
        float myDux = myD * xT[t0 + lane];
        float myE32 = __expf(myD * d32);
        ssum += myD;

        #pragma unroll 8
        for (int i = 0; i < 32; i++) {
            float du  = __shfl_sync(FULL, myD,   i);
            float dux = __shfl_sync(FULL, myDux, i);
            float e0  = __expf(du * A0);
            float e1  = uni ? e0 * __shfl_sync(FULL, myE32, i)
                            : __expf(du * A1);
            h0 = fmaf(e0, h0, dux * sB[i][lane]);
            h1 = fmaf(e1, h1, dux * sB[i][32 + lane]);
        }
    }
    float S = ssum;
    #pragma unroll
    for (int o = 16; o > 0; o >>= 1) S += __shfl_xor_sync(FULL, S, o);
    if (lane == 0) g_S[d * NC + c] = S;
    float* he = g_hend + ((size_t)c * DINNER + d) * DSTATE;
    he[lane] = h0;
    he[32 + lane] = h1;
}

// ---------------- pass 2: chain chunk-initial states ----------------
__global__ void scan_pass2(const float* __restrict__ A_log)
{
    int idx = blockIdx.x * 256 + threadIdx.x;
    int d = idx >> 6, n = idx & 63;
    float An = -expf(A_log[d * DSTATE + n]);
    float h = 0.f;
    #pragma unroll
    for (int c = 0; c < NC; c++) {
        g_hstart[((size_t)c * DINNER + d) * DSTATE + n] = h;
        if (c < NC - 1) {
            float E = __expf(An * g_S[d * NC + c]);
            h = fmaf(E, h, g_hend[((size_t)c * DINNER + d) * DSTATE + n]);
        }
    }
}

// ---------------- pass 3: y-producing scan, fused transpose + fp16 split out ----------------
__global__ __launch_bounds__(256)
void scan_pass3(const float* __restrict__ A_log, const float* __restrict__ Dp)
{
    __shared__ __align__(16) float sD[32][132];
    __shared__ float sY[32][9];
    const unsigned FULL = 0xffffffffu;
    int tid = threadIdx.x, lane = tid & 31, w = tid >> 5;
    int d0 = blockIdx.x * 8;
    int d = d0 + w;
    int c = blockIdx.y;

    float A0  = -expf(A_log[d * DSTATE + lane]);
    float A1  = -expf(A_log[d * DSTATE + 32 + lane]);
    float d32 = A1 - A0;
    bool uni  = __all_sync(FULL, __shfl_sync(FULL, d32, 0) == d32);
    float Dpd = Dp[d];

    const float* hs = g_hstart + ((size_t)c * DINNER + d) * DSTATE;
    float h0 = hs[lane];
    float h1 = hs[32 + lane];

    const float* xT  = g_xiT + (size_t)d * SEQ;
    const float* zT  = g_zsT + (size_t)d * SEQ;
    const float* dTp = g_dT  + (size_t)d * SEQ;
    const int tbeg = c * LC;

    const int ot = tid >> 3, od = tid & 7;

    for (int t0 = tbeg; t0 < tbeg + LC; t0 += 32) {
        __syncthreads();
        for (int i = tid; i < 32 * 32; i += 256) {
            int r = i >> 5, q = (i & 31) << 2;
            *(float4*)&sD[r][q] =
                *(const float4*)&g_dbc[(size_t)(t0 + r) * DBCCOLS + 32 + q];
        }
        __syncthreads();

        float myD   = dTp[t0 + lane];
        float myX   = xT[t0 + lane];
        float myZ   = zT[t0 + lane];
        float myDux = myD * myX;
        float myE32 = __expf(myD * d32);

        float p[32];
        #pragma unroll
        for (int i = 0; i < 32; i++) {
            float du  = __shfl_sync(FULL, myD,   i);
            float dux = __shfl_sync(FULL, myDux, i);
            float e0  = __expf(du * A0);
            float e1  = uni ? e0 * __shfl_sync(FULL, myE32, i)
                            : __expf(du * A1);
            h0 = fmaf(e0, h0, dux * sD[i][lane]);
            h1 = fmaf(e1, h1, dux * sD[i][32 + lane]);
            p[i] = fmaf(h0, sD[i][64 + lane], h1 * sD[i][96 + lane]);
        }

        #pragma unroll
        for (int o = 16; o >= 1; o >>= 1) {
            bool hi = (lane & o) != 0;
            #pragma unroll
            for (int jj = 0; jj < o; jj++) {
                float keep = hi ? p[o + jj] : p[jj];
                float send = hi ? p[jj] : p[o + jj];
                p[jj] = keep + __shfl_xor_sync(FULL, send, o);
            }
        }

        sY[lane][w] = (p[0] + Dpd * myX) * myZ;
        __syncthreads();

        float v = sY[ot][od];
        __half h = __float2half_rn(v);
        __half l = __float2half_rn(v - __half2float(h));
        size_t oidx = (size_t)(t0 + ot) * DINNER + d0 + od;
        g_yh[oidx] = h;
        g_yl[oidx] = l;
    }
}

// ---------------- launcher ----------------
extern "C" void kernel_launch(void* const* d_in, const int* in_sizes, int n_in,
                              void* d_out, int out_size)
{
    const float* x      = (const float*)d_in[0];
    const float* ln_g   = (const float*)d_in[1];
    const float* ln_b   = (const float*)d_in[2];
    const float* Win    = (const float*)d_in[3];
    const float* conv_w = (const float*)d_in[4];
    const float* conv_b = (const float*)d_in[5];
    const float* Wx     = (const float*)d_in[6];
    const float* Wdt    = (const float*)d_in[7];
    const float* bdt    = (const float*)d_in[8];
    const float* A_log  = (const float*)d_in[9];
    const float* Dp     = (const float*)d_in[10];
    const float* Wout   = (const float*)d_in[11];
    float* out = (float*)d_out;

    float *p_xz, *p_dbcp, *p_dT, *p_outp;
    cudaGetSymbolAddress((void**)&p_xz,   g_xz);
    cudaGetSymbolAddress((void**)&p_dbcp, g_dbcp);
    cudaGetSymbolAddress((void**)&p_dT,   g_dT);
    cudaGetSymbolAddress((void**)&p_outp, g_outp);
    __half *p_xnh, *p_xnl, *p_Winh, *p_xih, *p_xil, *p_Wxh;
    __half *p_dth, *p_Wdth, *p_Wdtl, *p_yh, *p_yl, *p_Wouth;
    cudaGetSymbolAddress((void**)&p_xnh,   g_xnh);
    cudaGetSymbolAddress((void**)&p_xnl,   g_xnl);
    cudaGetSymbolAddress((void**)&p_Winh,  g_Winh);
    cudaGetSymbolAddress((void**)&p_xih,   g_xih);
    cudaGetSymbolAddress((void**)&p_xil,   g_xil);
    cudaGetSymbolAddress((void**)&p_Wxh,   g_Wxh);
    cudaGetSymbolAddress((void**)&p_dth,   g_dth);
    cudaGetSymbolAddress((void**)&p_Wdth,  g_Wdth);
    cudaGetSymbolAddress((void**)&p_Wdtl,  g_Wdtl);
    cudaGetSymbolAddress((void**)&p_yh,    g_yh);
    cudaGetSymbolAddress((void**)&p_yl,    g_yl);
    cudaGetSymbolAddress((void**)&p_Wouth, g_Wouth);

    // dynamic smem: (2*BM + BN) * 40 halves * 2B * 2 bufs
    const int smem_128 = (2 * 128 + 128) * 40 * 2 * 2;   // 61440
    const int smem_64  = (2 * 128 + 64) * 40 * 2 * 2;    // 51200
    cudaFuncSetAttribute(mma_gemm<128, 128, 0, false, true>,
        cudaFuncAttributeMaxDynamicSharedMemorySize, smem_128);
    cudaFuncSetAttribute(mma_gemm<128, 64, 0, true, false>,
        cudaFuncAttributeMaxDynamicSharedMemorySize, smem_64);
    cudaFuncSetAttribute(mma_gemm<128, 128, 2, false, false>,
        cudaFuncAttributeMaxDynamicSharedMemorySize, smem_128);
    cudaFuncSetAttribute(mma_gemm<128, 64, 0, false, false>,
        cudaFuncAttributeMaxDynamicSharedMemorySize, smem_64);

    // 0. split all weights (one launch)
    split_all_kernel<<<1728, 256>>>(Win, Wx, Wdt, Wout);

    // 1. LayerNorm -> xn hi/lo
    ln_kernel<<<SEQ, 256>>>(x, ln_g, ln_b);

    // 2. xz = xn @ Win^T  [2048 x 2048 x 512]  one full-wave launch;
    //    z columns (bn >= 1024) use 1-pass fp16 (gate-only accuracy)
    mma_gemm<128, 128, 0, false, true><<<dim3(16, 16), 256, smem_128>>>(
        p_xnh, p_xnl, DMODEL, p_Winh, DMODEL,
        p_xz, XZCOLS, SEQ, XZCOLS, DMODEL, nullptr);

    // 3. conv + silu -> xi hi/lo, xiT, zsT
    conv_kernel<<<dim3(SEQ / 32, DINNER / 32), 256>>>(conv_w, conv_b);

    // 4. dbc = xi @ Wx^T  [2048 x 160 x 1024]  split-K=4 + fused reduce/dt-emit
    mma_gemm<128, 64, 0, true, false><<<dim3(3, 16, NSPLIT), 256, smem_64>>>(
        p_xih, p_xil, DINNER, p_Wxh, DINNER,
        p_dbcp, DBCCOLS, SEQ, DBCCOLS, DINNER / NSPLIT, nullptr);
    reduce4_kernel<<<SEQ * DBCCOLS / 1024, 256>>>();

    // 5. delta^T = softplus(Wdt @ dt^T + bdt)  [1024 x 2048 x 32]
    mma_gemm<128, 128, 2, false, false><<<dim3(16, 8), 256, smem_128>>>(
        p_Wdth, p_Wdtl, DTRANK, p_dth, DTRANK,
        p_dT, SEQ, DINNER, SEQ, DTRANK, bdt);

    // 6. chunked selective scan; pass3 emits y hi/lo [t][d] directly
    scan_pass1<<<dim3(DINNER / 8, NC - 1), 256>>>(A_log);
    scan_pass2<<<DINNER * DSTATE / 256, 256>>>(A_log);
    scan_pass3<<<dim3(DINNER / 8, NC), 256>>>(A_log, Dp);

    // 7. out = y @ Wout^T  [2048 x 512 x 1024]  split-K=4, then +resid
    mma_gemm<128, 64, 0, false, false><<<dim3(8, 16, G4SPLIT), 256, smem_64>>>(
        p_yh, p_yl, DINNER, p_Wouth, DINNER,
        p_outp, DMODEL, SEQ, DMODEL, DINNER / G4SPLIT, nullptr);
    reduce4_resid_kernel<<<SEQ * DMODEL / 1024, 256>>>(x, out);
}

// round 16
// speedup vs baseline: 1.1131x; 1.1131x over previous
#include <cuda_runtime.h>
#include <cuda_fp16.h>
#include <math.h>
#include <stdint.h>

// ---------------- problem constants ----------------
#define SEQ     2048
#define DMODEL  512
#define DINNER  1024
#define DSTATE  64
#define DTRANK  32
#define DCONV   4
#define XZCOLS  (2*DINNER)          // 2048
#define DBCCOLS (DTRANK + 2*DSTATE) // 160
#define NSPLIT  4
#define G4SPLIT 2
#define NC      8                   // scan chunks
#define LC      (SEQ/NC)            // 256 timesteps per chunk

// ---------------- scratch (device globals; no allocation) ----------------
__device__ float g_xz    [SEQ*XZCOLS];
__device__ float g_xiT   [DINNER*SEQ];
__device__ float g_zsT   [DINNER*SEQ];
__device__ float g_dbcp  [NSPLIT*SEQ*DBCCOLS];
__device__ float g_dbc   [SEQ*DBCCOLS];
__device__ float g_dT    [DINNER*SEQ];
__device__ float g_S     [DINNER*NC];
__device__ float g_hend  [NC*DINNER*DSTATE];
__device__ float g_outp  [G4SPLIT*SEQ*DMODEL];   // G4 split-K partials

// fp16 operand buffers
__device__ __align__(16) __half g_xnh  [SEQ*DMODEL];
__device__ __align__(16) __half g_Winh [XZCOLS*DMODEL];
__device__ __align__(16) __half g_xih  [SEQ*DINNER];
__device__ __align__(16) __half g_xil  [SEQ*DINNER];
__device__ __align__(16) __half g_Wxh  [DBCCOLS*DINNER];
__device__ __align__(16) __half g_dth  [SEQ*DTRANK];
__device__ __align__(16) __half g_Wdth [DINNER*DTRANK];
__device__ __align__(16) __half g_Wdtl [DINNER*DTRANK];
__device__ __align__(16) __half g_yh   [SEQ*DINNER];
__device__ __align__(16) __half g_Wouth[DMODEL*DINNER];

// ---------------- helpers ----------------
__device__ __forceinline__ float siluf(float x) { return x / (1.0f + __expf(-x)); }
__device__ __forceinline__ float softplusf(float x) {
    return (x > 15.0f) ? x : log1pf(__expf(x));
}
__device__ __forceinline__ uint32_t smem_u32(const void* p) {
    uint32_t a;
    asm("{ .reg .u64 t; cvta.to.shared.u64 t, %1; cvt.u32.u64 %0, t; }"
        : "=r"(a) : "l"(p));
    return a;
}
__device__ __forceinline__ void ldsm4(uint32_t& r0, uint32_t& r1,
                                      uint32_t& r2, uint32_t& r3, uint32_t addr) {
    asm volatile("ldmatrix.sync.aligned.m8n8.x4.shared.b16 {%0,%1,%2,%3}, [%4];"
                 : "=r"(r0), "=r"(r1), "=r"(r2), "=r"(r3) : "r"(addr));
}
__device__ __forceinline__ void mma_f16(float* c, uint32_t a0, uint32_t a1,
                                        uint32_t a2, uint32_t a3,
                                        uint32_t b0, uint32_t b1) {
    asm volatile(
        "mma.sync.aligned.m16n8k16.row.col.f32.f16.f16.f32 "
        "{%0,%1,%2,%3}, {%4,%5,%6,%7}, {%8,%9}, {%0,%1,%2,%3};"
        : "+f"(c[0]), "+f"(c[1]), "+f"(c[2]), "+f"(c[3])
        : "r"(a0), "r"(a1), "r"(a2), "r"(a3), "r"(b0), "r"(b1));
}
__device__ __forceinline__ uint32_t hpack2(float x, float y) {
    __half2 h = __floats2half2_rn(x, y);
    return *(uint32_t*)&h;
}
__device__ __forceinline__ void splitH2(float x, float y,
                                        uint32_t& hi, uint32_t& lo) {
    __half2 h = __floats2half2_rn(x, y);
    __half2 l = __floats2half2_rn(x - __low2float(h), y - __high2float(h));
    hi = *(uint32_t*)&h;
    lo = *(uint32_t*)&l;
}

// ---------------- fused weight split (one launch) ----------------
__global__ void split_all_kernel(const float* __restrict__ Win,
                                 const float* __restrict__ Wx,
                                 const float* __restrict__ Wdt,
                                 const float* __restrict__ Wout)
{
    int b = blockIdx.x;
    if (b < 1184 || b >= 1216) {
        const float* src;
        __half* hi;
        int off;
        if (b < 1024)      { src = Win;  hi = g_Winh;  off = b; }
        else if (b < 1184) { src = Wx;   hi = g_Wxh;   off = b - 1024; }
        else               { src = Wout; hi = g_Wouth; off = b - 1216; }
        int i = (off * 256 + threadIdx.x) * 4;
        float4 v = *(const float4*)&src[i];
        *(uint2*)&hi[i] = make_uint2(hpack2(v.x, v.y), hpack2(v.z, v.w));
    } else {
        int off = b - 1184;
        int i = (off * 256 + threadIdx.x) * 4;
        float4 v = *(const float4*)&Wdt[i];
        uint32_t h0, l0, h1, l1;
        splitH2(v.x, v.y, h0, l0);
        splitH2(v.z, v.w, h1, l1);
        *(uint2*)&g_Wdth[i] = make_uint2(h0, h1);
        *(uint2*)&g_Wdtl[i] = make_uint2(l0, l1);
    }
}

// ---------------- LayerNorm: one block per token, emits fp16 hi ----------------
__global__ void ln_kernel(const float* __restrict__ x,
                          const float* __restrict__ g,
                          const float* __restrict__ b)
{
    int t   = blockIdx.x;
    int tid = threadIdx.x;
    const float* xr = x + t * DMODEL;
    float2 v = *(const float2*)&xr[tid * 2];
    float s = v.x + v.y;
    float q = v.x * v.x + v.y * v.y;
    #pragma unroll
    for (int o = 16; o > 0; o >>= 1) {
        s += __shfl_xor_sync(0xffffffffu, s, o);
        q += __shfl_xor_sync(0xffffffffu, q, o);
    }
    __shared__ float ss[8], qq[8];
    int lane = tid & 31, w = tid >> 5;
    if (lane == 0) { ss[w] = s; qq[w] = q; }
    __syncthreads();
    s = 0.f; q = 0.f;
    #pragma unroll
    for (int i = 0; i < 8; i++) { s += ss[i]; q += qq[i]; }
    float mu  = s * (1.0f / DMODEL);
    float var = q * (1.0f / DMODEL) - mu * mu;
    float r   = rsqrtf(var + 1e-5f);
    float2 gg = *(const float2*)&g[tid * 2];
    float2 bb = *(const float2*)&b[tid * 2];
    float ox = (v.x - mu) * r * gg.x + bb.x;
    float oy = (v.y - mu) * r * gg.y + bb.y;
    *(uint32_t*)&g_xnh[t * DMODEL + tid * 2] = hpack2(ox, oy);
}

// ---------------- fp16 split HMMA GEMM (PASSES = 1 or 2) ----------------
// C[m][n] = sum_k A[m][k]*B[n][k]; A fp16 hi (+lo if PASSES==2), B fp16 hi.
// PASSES==2: D = Ahi*Bhi + Alo*Bhi.  PASSES==1: D = Ahi*Bhi.
// 32 fp32-k per tile; rows padded to 40 halves. 8 warps 2(m) x 4(n).
// split-K via blockIdx.z. EPI: 0 none, 2 softplus(acc+ep[row]). NGUARD vs N.
template<int BM, int BN, int EPI, bool NGUARD, int PASSES>
__global__ __launch_bounds__(256, 2)
void mma_gemm(const __half* __restrict__ Ah,
              const __half* __restrict__ Al, int lda,
              const __half* __restrict__ Bh, int ldb,
              float* __restrict__ C, int ldc,
              int M, int N, int K, const float* __restrict__ ep)
{
    constexpr int S = 40;
    constexpr int MT = (BM / 2) / 16;
    constexpr int NT = (BN / 4) / 8;
    constexpr int AIT = BM / 64;
    constexpr int BIT = BN / 64;
    constexpr int PERBUF = (PASSES * BM + BN) * S;

    extern __shared__ __align__(16) __half sm[];
    const uint32_t sb = smem_u32(sm);

    const int tid = threadIdx.x, lane = tid & 31, wid = tid >> 5;
    const int bm = blockIdx.y * BM, bn = blockIdx.x * BN;
    const int z = blockIdx.z;
    const int kbeg = z * K;
    C += (size_t)z * M * ldc;
    const int wm0 = (wid & 1) * (BM / 2);
    const int wn0 = (wid >> 1) * (BN / 4);

    const int lA_r = lane & 15;
    const int lA_c = (lane >> 4) << 3;
    const int lB_r = (lane & 7) + ((lane >> 4) << 3);
    const int lB_c = ((lane >> 3) & 1) << 3;

    float acc[MT][NT][4];
    #pragma unroll
    for (int i = 0; i < MT; i++)
        #pragma unroll
        for (int j = 0; j < NT; j++)
            #pragma unroll
            for (int q = 0; q < 4; q++) acc[i][j][q] = 0.0f;

    uint4 vah[AIT], val[AIT], vbh[BIT];

    auto loadG = [&](int k0) {
        #pragma unroll
        for (int i = 0; i < AIT; i++) {
            int idx = tid + i * 256;
            int r = idx >> 2, ch = (idx & 3) << 3;
            size_t s = (size_t)(bm + r) * lda + k0 + ch;
            vah[i] = *(const uint4*)&Ah[s];
            if (PASSES == 2) val[i] = *(const uint4*)&Al[s];
        }
        #pragma unroll
        for (int i = 0; i < BIT; i++) {
            int idx = tid + i * 256;
            int r = idx >> 2, ch = (idx & 3) << 3;
            int rr = bn + r;
            if (NGUARD) rr = min(rr, N - 1);
            size_t s = (size_t)rr * ldb + k0 + ch;
            vbh[i] = *(const uint4*)&Bh[s];
        }
    };
    auto storeS = [&](int buf) {
        const int oAh = buf * PERBUF;
        const int oAl = oAh + BM * S;
        const int oBh = oAh + PASSES * BM * S;
        #pragma unroll
        for (int i = 0; i < AIT; i++) {
            int idx = tid + i * 256;
            int r = idx >> 2, ch = (idx & 3) << 3;
            *(uint4*)&sm[oAh + r * S + ch] = vah[i];
            if (PASSES == 2) *(uint4*)&sm[oAl + r * S + ch] = val[i];
        }
        #pragma unroll
        for (int i = 0; i < BIT; i++) {
            int idx = tid + i * 256;
            int r = idx >> 2, ch = (idx & 3) << 3;
            *(uint4*)&sm[oBh + r * S + ch] = vbh[i];
        }
    };
    auto compute = [&](int buf) {
        const int oAh = buf * PERBUF;
        const int oAl = oAh + BM * S;
        const int oBh = oAh + PASSES * BM * S;
        #pragma unroll
        for (int kk = 0; kk < 32; kk += 16) {
            uint32_t af[MT][4];
            uint32_t bh[NT / 2][4];
            #pragma unroll
            for (int mi = 0; mi < MT; mi++) {
                uint32_t addr = sb + (uint32_t)(oAh +
                    (wm0 + mi * 16 + lA_r) * S + kk + lA_c) * 2;
                ldsm4(af[mi][0], af[mi][1], af[mi][2], af[mi][3], addr);
            }
            #pragma unroll
            for (int nj = 0; nj < NT / 2; nj++) {
                uint32_t addr = sb + (uint32_t)(oBh +
                    (wn0 + nj * 16 + lB_r) * S + kk + lB_c) * 2;
                ldsm4(bh[nj][0], bh[nj][1], bh[nj][2], bh[nj][3], addr);
            }
            #pragma unroll
            for (int mi = 0; mi < MT; mi++)
                #pragma unroll
                for (int ni = 0; ni < NT; ni++)
                    mma_f16(acc[mi][ni],
                            af[mi][0], af[mi][1], af[mi][2], af[mi][3],
                            bh[ni >> 1][(ni & 1) * 2],
                            bh[ni >> 1][(ni & 1) * 2 + 1]);
            if (PASSES == 2) {
                #pragma unroll
                for (int mi = 0; mi < MT; mi++) {
                    uint32_t addr = sb + (uint32_t)(oAl +
                        (wm0 + mi * 16 + lA_r) * S + kk + lA_c) * 2;
                    ldsm4(af[mi][0], af[mi][1], af[mi][2], af[mi][3], addr);
                }
                #pragma unroll
                for (int mi = 0; mi < MT; mi++)
                    #pragma unroll
                    for (int ni = 0; ni < NT; ni++)
                        mma_f16(acc[mi][ni],
                                af[mi][0], af[mi][1], af[mi][2], af[mi][3],
                                bh[ni >> 1][(ni & 1) * 2],
                                bh[ni >> 1][(ni & 1) * 2 + 1]);
            }
        }
    };

    loadG(kbeg);
    storeS(0);
    __syncthreads();
    int cur = 0;
    const int KT = K / 32;
    for (int kt = 0; kt < KT; kt++) {
        bool has = (kt + 1) < KT;
        if (has) loadG(kbeg + (kt + 1) * 32);
        compute(cur);
        if (has) {
            storeS(cur ^ 1);
            __syncthreads();
            cur ^= 1;
        }
    }

    #pragma unroll
    for (int mi = 0; mi < MT; mi++) {
        #pragma unroll
        for (int ni = 0; ni < NT; ni++) {
            int colb = bn + wn0 + ni * 8;
            if (NGUARD && colb >= N) continue;
            int row = bm + wm0 + mi * 16 + (lane >> 2);
            int col = colb + (lane & 3) * 2;
            float2 v0 = make_float2(acc[mi][ni][0], acc[mi][ni][1]);
            float2 v1 = make_float2(acc[mi][ni][2], acc[mi][ni][3]);
            if (EPI == 2) {
                float b0 = ep[row], b1 = ep[row + 8];
                v0.x = softplusf(v0.x + b0); v0.y = softplusf(v0.y + b0);
                v1.x = softplusf(v1.x + b1); v1.y = softplusf(v1.y + b1);
            }
            *(float2*)&C[(size_t)row * ldc + col] = v0;
            *(float2*)&C[(size_t)(row + 8) * ldc + col] = v1;
        }
    }
}

// reduce the 4 split-K partials (dbc) + fused dt fp16-hi emit
__global__ void reduce4_kernel()
{
    int i = (blockIdx.x * 256 + threadIdx.x) * 4;
    const int TOT = SEQ * DBCCOLS;
    float4 a = *(const float4*)&g_dbcp[0 * TOT + i];
    float4 b = *(const float4*)&g_dbcp[1 * TOT + i];
    float4 c = *(const float4*)&g_dbcp[2 * TOT + i];
    float4 d = *(const float4*)&g_dbcp[3 * TOT + i];
    float4 o;
    o.x = (a.x + b.x) + (c.x + d.x);
    o.y = (a.y + b.y) + (c.y + d.y);
    o.z = (a.z + b.z) + (c.z + d.z);
    o.w = (a.w + b.w) + (c.w + d.w);
    *(float4*)&g_dbc[i] = o;
    int t = i / DBCCOLS, cc = i % DBCCOLS;
    if (cc < DTRANK) {
        *(uint2*)&g_dth[t * DTRANK + cc] =
            make_uint2(hpack2(o.x, o.y), hpack2(o.z, o.w));
    }
}

// reduce 2 split-K partials of G4 and add residual -> final out
__global__ void reduce2_resid_kernel(const float* __restrict__ x,
                                     float* __restrict__ out)
{
    int i = (blockIdx.x * 256 + threadIdx.x) * 4;
    const int TOT = SEQ * DMODEL;
    float4 a = *(const float4*)&g_outp[i];
    float4 b = *(const float4*)&g_outp[TOT + i];
    float4 r = *(const float4*)&x[i];
    float4 o;
    o.x = a.x + b.x + r.x;
    o.y = a.y + b.y + r.y;
    o.z = a.z + b.z + r.z;
    o.w = a.w + b.w + r.w;
    *(float4*)&out[i] = o;
}

// ---------------- depthwise conv + silu: emits xi hi/lo (fp16), xiT, zsT ----------------
__global__ __launch_bounds__(256)
void conv_kernel(const float* __restrict__ cw, const float* __restrict__ cb)
{
    __shared__ float sxz[35][33];
    __shared__ float sxi[32][33];
    __shared__ float szs[32][33];
    int t0 = blockIdx.x * 32, c0 = blockIdx.y * 32;
    int tid = threadIdx.x;

    for (int i = tid; i < 35 * 32; i += 256) {
        int r = i >> 5, c = i & 31;
        int gt = t0 + r - 3;
        sxz[r][c] = (gt >= 0) ? g_xz[gt * XZCOLS + c0 + c] : 0.0f;
    }
    for (int i = tid; i < 32 * 32; i += 256) {
        int r = i >> 5, c = i & 31;
        float z = g_xz[(t0 + r) * XZCOLS + DINNER + c0 + c];
        szs[r][c] = siluf(z);
    }
    __syncthreads();

    int cl = tid & 31, tq = tid >> 5;
    float4 w = *(const float4*)&cw[(c0 + cl) * 4];
    float bb = cb[c0 + cl];
    #pragma unroll
    for (int s = 0; s < 4; s++) {
        int tl = tq + s * 8;
        float v = sxz[tl + 0][cl] * w.x + sxz[tl + 1][cl] * w.y +
                  sxz[tl + 2][cl] * w.z + sxz[tl + 3][cl] * w.w + bb;
        v = siluf(v);
        __half h = __float2half_rn(v);
        __half l = __float2half_rn(v - __half2float(h));
        g_xih[(size_t)(t0 + tl) * DINNER + c0 + cl] = h;
        g_xil[(size_t)(t0 + tl) * DINNER + c0 + cl] = l;
        sxi[tl][cl] = v;
    }
    __syncthreads();

    int tl2 = tid & 31, cq = tid >> 5;
    #pragma unroll
    for (int s = 0; s < 4; s++) {
        int cl2 = cq + s * 8;
        g_xiT[(size_t)(c0 + cl2) * SEQ + t0 + tl2] = sxi[tl2][cl2];
        g_zsT[(size_t)(c0 + cl2) * SEQ + t0 + tl2] = szs[tl2][cl2];
    }
}

// ---------------- chunked scan, pass 1 (chunks 0..NC-2 only) ----------------
__global__ __launch_bounds__(256)
void scan_pass1(const float* __restrict__ A_log)
{
    __shared__ __align__(16) float sB[32][68];
    const unsigned FULL = 0xffffffffu;
    int tid = threadIdx.x, lane = tid & 31, w = tid >> 5;
    int d = blockIdx.x * 8 + w;
    int c = blockIdx.y;

    float A0  = -expf(A_log[d * DSTATE + lane]);
    float A1  = -expf(A_log[d * DSTATE + 32 + lane]);
    float d32 = A1 - A0;
    bool uni  = __all_sync(FULL, __shfl_sync(FULL, d32, 0) == d32);
    float h0 = 0.f, h1 = 0.f, ssum = 0.f;

    const float* xT  = g_xiT + (size_t)d * SEQ;
    const float* dTp = g_dT  + (size_t)d * SEQ;
    const int tbeg = c * LC;

    for (int t0 = tbeg; t0 < tbeg + LC; t0 += 32) {
        __syncthreads();
        for (int i = tid; i < 32 * 16; i += 256) {
            int r = i >> 4, q = (i & 15) << 2;
            *(float4*)&sB[r][q] =
                *(const float4*)&g_dbc[(size_t)(t0 + r) * DBCCOLS + 32 + q];
        }
        __syncthreads();

        float myD   = dTp[t0 + lane];
        float myDux = myD * xT[t0 + lane];
        float myE32 = __expf(myD * d32);
        ssum += myD;

        #pragma unroll 8
        for (int i = 0; i < 32; i++) {
            float du  = __shfl_sync(FULL, myD,   i);
            float dux = __shfl_sync(FULL, myDux, i);
            float e0  = __expf(du * A0);
            float e1  = uni ? e0 * __shfl_sync(FULL, myE32, i)
                            : __expf(du * A1);
            h0 = fmaf(e0, h0, dux * sB[i][lane]);
            h1 = fmaf(e1, h1, dux * sB[i][32 + lane]);
        }
    }
    float S = ssum;
    #pragma unroll
    for (int o = 16; o > 0; o >>= 1) S += __shfl_xor_sync(FULL, S, o);
    if (lane == 0) g_S[d * NC + c] = S;
    float* he = g_hend + ((size_t)c * DINNER + d) * DSTATE;
    he[lane] = h0;
    he[32 + lane] = h1;
}

// ---------------- pass 3: y scan with inline chunk-chain init + fp16 out ----------------
__global__ __launch_bounds__(256)
void scan_pass3(const float* __restrict__ A_log, const float* __restrict__ Dp)
{
    __shared__ __align__(16) float sD[32][132];
    __shared__ float sY[32][9];
    const unsigned FULL = 0xffffffffu;
    int tid = threadIdx.x, lane = tid & 31, w = tid >> 5;
    int d0 = blockIdx.x * 8;
    int d = d0 + w;
    int c = blockIdx.y;

    float A0  = -expf(A_log[d * DSTATE + lane]);
    float A1  = -expf(A_log[d * DSTATE + 32 + lane]);
    float d32 = A1 - A0;
    bool uni  = __all_sync(FULL, __shfl_sync(FULL, d32, 0) == d32);
    float Dpd = Dp[d];

    // inline pass2: chain chunks 0..c-1 (exact same arithmetic as before)
    float h0 = 0.f, h1 = 0.f;
    for (int cc = 0; cc < c; cc++) {
        float Sv = g_S[d * NC + cc];
        float E0 = __expf(A0 * Sv);
        float E1 = __expf(A1 * Sv);
        const float* he = g_hend + ((size_t)cc * DINNER + d) * DSTATE;
        h0 = fmaf(E0, h0, he[lane]);
        h1 = fmaf(E1, h1, he[32 + lane]);
    }

    const float* xT  = g_xiT + (size_t)d * SEQ;
    const float* zT  = g_zsT + (size_t)d * SEQ;
    const float* dTp = g_dT  + (size_t)d * SEQ;
    const int tbeg = c * LC;

    const int ot = tid >> 3, od = tid & 7;

    for (int t0 = tbeg; t0 < tbeg + LC; t0 += 32) {
        __syncthreads();
        for (int i = tid; i < 32 * 32; i += 256) {
            int r = i >> 5, q = (i & 31) << 2;
            *(float4*)&sD[r][q] =
                *(const float4*)&g_dbc[(size_t)(t0 + r) * DBCCOLS + 32 + q];
        }
        __syncthreads();

        float myD   = dTp[t0 + lane];
        float myX   = xT[t0 + lane];
        float myZ   = zT[t0 + lane];
        float myDux = myD * myX;
        float myE32 = __expf(myD * d32);

        float p[32];
        #pragma unroll
        for (int i = 0; i < 32; i++) {
            float du  = __shfl_sync(FULL, myD,   i);
            float dux = __shfl_sync(FULL, myDux, i);
            float e0  = __expf(du * A0);
            float e1  = uni ? e0 * __shfl_sync(FULL, myE32, i)
                            : __expf(du * A1);
            h0 = fmaf(e0, h0, dux * sD[i][lane]);
            h1 = fmaf(e1, h1, dux * sD[i][32 + lane]);
            p[i] = fmaf(h0, sD[i][64 + lane], h1 * sD[i][96 + lane]);
        }

        #pragma unroll
        for (int o = 16; o >= 1; o >>= 1) {
            bool hi = (lane & o) != 0;
            #pragma unroll
            for (int jj = 0; jj < o; jj++) {
                float keep = hi ? p[o + jj] : p[jj];
                float send = hi ? p[jj] : p[o + jj];
                p[jj] = keep + __shfl_xor_sync(FULL, send, o);
            }
        }

        sY[lane][w] = (p[0] + Dpd * myX) * myZ;
        __syncthreads();

        float v = sY[ot][od];
        g_yh[(size_t)(t0 + ot) * DINNER + d0 + od] = __float2half_rn(v);
    }
}

// ---------------- launcher ----------------
extern "C" void kernel_launch(void* const* d_in, const int* in_sizes, int n_in,
                              void* d_out, int out_size)
{
    const float* x      = (const float*)d_in[0];
    const float* ln_g   = (const float*)d_in[1];
    const float* ln_b   = (const float*)d_in[2];
    const float* Win    = (const float*)d_in[3];
    const float* conv_w = (const float*)d_in[4];
    const float* conv_b = (const float*)d_in[5];
    const float* Wx     = (const float*)d_in[6];
    const float* Wdt    = (const float*)d_in[7];
    const float* bdt    = (const float*)d_in[8];
    const float* A_log  = (const float*)d_in[9];
    const float* Dp     = (const float*)d_in[10];
    const float* Wout   = (const float*)d_in[11];
    float* out = (float*)d_out;

    float *p_xz, *p_dbcp, *p_dT, *p_outp;
    cudaGetSymbolAddress((void**)&p_xz,   g_xz);
    cudaGetSymbolAddress((void**)&p_dbcp, g_dbcp);
    cudaGetSymbolAddress((void**)&p_dT,   g_dT);
    cudaGetSymbolAddress((void**)&p_outp, g_outp);
    __half *p_xnh, *p_Winh, *p_xih, *p_xil, *p_Wxh;
    __half *p_dth, *p_Wdth, *p_Wdtl, *p_yh, *p_Wouth;
    cudaGetSymbolAddress((void**)&p_xnh,   g_xnh);
    cudaGetSymbolAddress((void**)&p_Winh,  g_Winh);
    cudaGetSymbolAddress((void**)&p_xih,   g_xih);
    cudaGetSymbolAddress((void**)&p_xil,   g_xil);
    cudaGetSymbolAddress((void**)&p_Wxh,   g_Wxh);
    cudaGetSymbolAddress((void**)&p_dth,   g_dth);
    cudaGetSymbolAddress((void**)&p_Wdth,  g_Wdth);
    cudaGetSymbolAddress((void**)&p_Wdtl,  g_Wdtl);
    cudaGetSymbolAddress((void**)&p_yh,    g_yh);
    cudaGetSymbolAddress((void**)&p_Wouth, g_Wouth);

    // dynamic smem: (PASSES*BM + BN) * 40 halves * 2B * 2 bufs
    const int smem_1p_128 = (1 * 128 + 128) * 40 * 2 * 2;  // 40960
    const int smem_1p_64  = (1 * 128 + 64) * 40 * 2 * 2;   // 30720
    const int smem_2p_128 = (2 * 128 + 128) * 40 * 2 * 2;  // 61440
    const int smem_2p_64  = (2 * 128 + 64) * 40 * 2 * 2;   // 51200
    cudaFuncSetAttribute(mma_gemm<128, 128, 0, false, 1>,
        cudaFuncAttributeMaxDynamicSharedMemorySize, smem_1p_128);
    cudaFuncSetAttribute(mma_gemm<128, 64, 0, true, 2>,
        cudaFuncAttributeMaxDynamicSharedMemorySize, smem_2p_64);
    cudaFuncSetAttribute(mma_gemm<128, 128, 2, false, 2>,
        cudaFuncAttributeMaxDynamicSharedMemorySize, smem_2p_128);
    cudaFuncSetAttribute(mma_gemm<128, 64, 0, false, 1>,
        cudaFuncAttributeMaxDynamicSharedMemorySize, smem_1p_64);

    // 0. split all weights (one launch)
    split_all_kernel<<<1728, 256>>>(Win, Wx, Wdt, Wout);

    // 1. LayerNorm -> xn hi
    ln_kernel<<<SEQ, 256>>>(x, ln_g, ln_b);

    // 2. xz = xn @ Win^T  [2048 x 2048 x 512]  1-pass fp16, one full wave
    mma_gemm<128, 128, 0, false, 1><<<dim3(16, 16), 256, smem_1p_128>>>(
        p_xnh, nullptr, DMODEL, p_Winh, DMODEL,
        p_xz, XZCOLS, SEQ, XZCOLS, DMODEL, nullptr);

    // 3. conv + silu -> xi hi/lo, xiT, zsT
    conv_kernel<<<dim3(SEQ / 32, DINNER / 32), 256>>>(conv_w, conv_b);

    // 4. dbc = xi @ Wx^T  [2048 x 160 x 1024]  2-pass, split-K=4 + fused reduce
    mma_gemm<128, 64, 0, true, 2><<<dim3(3, 16, NSPLIT), 256, smem_2p_64>>>(
        p_xih, p_xil, DINNER, p_Wxh, DINNER,
        p_dbcp, DBCCOLS, SEQ, DBCCOLS, DINNER / NSPLIT, nullptr);
    reduce4_kernel<<<SEQ * DBCCOLS / 1024, 256>>>();

    // 5. delta^T = softplus(Wdt @ dt^T + bdt)  [1024 x 2048 x 32]  2-pass
    mma_gemm<128, 128, 2, false, 2><<<dim3(16, 8), 256, smem_2p_128>>>(
        p_Wdth, p_Wdtl, DTRANK, p_dth, DTRANK,
        p_dT, SEQ, DINNER, SEQ, DTRANK, bdt);

    // 6. chunked selective scan: pass1 (chunks 0..NC-2) then pass3 with
    //    inline chunk-chain init; pass3 emits y fp16 [t][d] directly
    scan_pass1<<<dim3(DINNER / 8, NC - 1), 256>>>(A_log);
    scan_pass3<<<dim3(DINNER / 8, NC), 256>>>(A_log, Dp);

    // 7. out = y @ Wout^T  [2048 x 512 x 1024]  1-pass fp16, split-K=2, +resid
    mma_gemm<128, 64, 0, false, 1><<<dim3(8, 16, G4SPLIT), 256, smem_1p_64>>>(
        p_yh, nullptr, DINNER, p_Wouth, DINNER,
        p_outp, DMODEL, SEQ, DMODEL, DINNER / G4SPLIT, nullptr);
    reduce2_resid_kernel<<<SEQ * DMODEL / 1024, 256>>>(x, out);
}

// round 17
// speedup vs baseline: 1.1342x; 1.0190x over previous
#include <cuda_runtime.h>
#include <cuda_fp16.h>
#include <math.h>
#include <stdint.h>

// ---------------- problem constants ----------------
#define SEQ     2048
#define DMODEL  512
#define DINNER  1024
#define DSTATE  64
#define DTRANK  32
#define DCONV   4
#define XZCOLS  (2*DINNER)          // 2048
#define DBCCOLS (DTRANK + 2*DSTATE) // 160
#define NSPLIT  4
#define G4SPLIT 2
#define NC      8                   // scan chunks
#define LC      (SEQ/NC)            // 256 timesteps per chunk

// ---------------- scratch (device globals; no allocation) ----------------
__device__ float g_xiT   [DINNER*SEQ];
__device__ float g_zsT   [DINNER*SEQ];
__device__ float g_dbcp  [NSPLIT*SEQ*DBCCOLS];
__device__ float g_dbc   [SEQ*DBCCOLS];
__device__ float g_dT    [DINNER*SEQ];
__device__ float g_S     [DINNER*NC];
__device__ float g_hend  [NC*DINNER*DSTATE];
__device__ float g_outp  [G4SPLIT*SEQ*DMODEL];   // G4 split-K partials

// fp16 buffers
__device__ __align__(16) __half g_xzh  [SEQ*XZCOLS];     // G1 output (fp16)
__device__ __align__(16) __half g_xnh  [SEQ*DMODEL];
__device__ __align__(16) __half g_Winh [XZCOLS*DMODEL];
__device__ __align__(16) __half g_xih  [SEQ*DINNER];
__device__ __align__(16) __half g_Wxh  [DBCCOLS*DINNER];
__device__ __align__(16) __half g_dth  [SEQ*DTRANK];
__device__ __align__(16) __half g_Wdth [DINNER*DTRANK];
__device__ __align__(16) __half g_Wdtl [DINNER*DTRANK];
__device__ __align__(16) __half g_yh   [SEQ*DINNER];
__device__ __align__(16) __half g_Wouth[DMODEL*DINNER];

// ---------------- helpers ----------------
__device__ __forceinline__ float siluf(float x) { return x / (1.0f + __expf(-x)); }
__device__ __forceinline__ float softplusf(float x) {
    return (x > 15.0f) ? x : log1pf(__expf(x));
}
__device__ __forceinline__ uint32_t smem_u32(const void* p) {
    uint32_t a;
    asm("{ .reg .u64 t; cvta.to.shared.u64 t, %1; cvt.u32.u64 %0, t; }"
        : "=r"(a) : "l"(p));
    return a;
}
__device__ __forceinline__ void ldsm4(uint32_t& r0, uint32_t& r1,
                                      uint32_t& r2, uint32_t& r3, uint32_t addr) {
    asm volatile("ldmatrix.sync.aligned.m8n8.x4.shared.b16 {%0,%1,%2,%3}, [%4];"
                 : "=r"(r0), "=r"(r1), "=r"(r2), "=r"(r3) : "r"(addr));
}
__device__ __forceinline__ void mma_f16(float* c, uint32_t a0, uint32_t a1,
                                        uint32_t a2, uint32_t a3,
                                        uint32_t b0, uint32_t b1) {
    asm volatile(
        "mma.sync.aligned.m16n8k16.row.col.f32.f16.f16.f32 "
        "{%0,%1,%2,%3}, {%4,%5,%6,%7}, {%8,%9}, {%0,%1,%2,%3};"
        : "+f"(c[0]), "+f"(c[1]), "+f"(c[2]), "+f"(c[3])
        : "r"(a0), "r"(a1), "r"(a2), "r"(a3), "r"(b0), "r"(b1));
}
__device__ __forceinline__ uint32_t hpack2(float x, float y) {
    __half2 h = __floats2half2_rn(x, y);
    return *(uint32_t*)&h;
}
__device__ __forceinline__ void splitH2(float x, float y,
                                        uint32_t& hi, uint32_t& lo) {
    __half2 h = __floats2half2_rn(x, y);
    __half2 l = __floats2half2_rn(x - __low2float(h), y - __high2float(h));
    hi = *(uint32_t*)&h;
    lo = *(uint32_t*)&l;
}

// ---------------- fused weight split (one launch) ----------------
__global__ void split_all_kernel(const float* __restrict__ Win,
                                 const float* __restrict__ Wx,
                                 const float* __restrict__ Wdt,
                                 const float* __restrict__ Wout)
{
    int b = blockIdx.x;
    if (b < 1184 || b >= 1216) {
        const float* src;
        __half* hi;
        int off;
        if (b < 1024)      { src = Win;  hi = g_Winh;  off = b; }
        else if (b < 1184) { src = Wx;   hi = g_Wxh;   off = b - 1024; }
        else               { src = Wout; hi = g_Wouth; off = b - 1216; }
        int i = (off * 256 + threadIdx.x) * 4;
        float4 v = *(const float4*)&src[i];
        *(uint2*)&hi[i] = make_uint2(hpack2(v.x, v.y), hpack2(v.z, v.w));
    } else {
        int off = b - 1184;
        int i = (off * 256 + threadIdx.x) * 4;
        float4 v = *(const float4*)&Wdt[i];
        uint32_t h0, l0, h1, l1;
        splitH2(v.x, v.y, h0, l0);
        splitH2(v.z, v.w, h1, l1);
        *(uint2*)&g_Wdth[i] = make_uint2(h0, h1);
        *(uint2*)&g_Wdtl[i] = make_uint2(l0, l1);
    }
}

// ---------------- LayerNorm: one block per token, emits fp16 hi ----------------
__global__ void ln_kernel(const float* __restrict__ x,
                          const float* __restrict__ g,
                          const float* __restrict__ b)
{
    int t   = blockIdx.x;
    int tid = threadIdx.x;
    const float* xr = x + t * DMODEL;
    float2 v = *(const float2*)&xr[tid * 2];
    float s = v.x + v.y;
    float q = v.x * v.x + v.y * v.y;
    #pragma unroll
    for (int o = 16; o > 0; o >>= 1) {
        s += __shfl_xor_sync(0xffffffffu, s, o);
        q += __shfl_xor_sync(0xffffffffu, q, o);
    }
    __shared__ float ss[8], qq[8];
    int lane = tid & 31, w = tid >> 5;
    if (lane == 0) { ss[w] = s; qq[w] = q; }
    __syncthreads();
    s = 0.f; q = 0.f;
    #pragma unroll
    for (int i = 0; i < 8; i++) { s += ss[i]; q += qq[i]; }
    float mu  = s * (1.0f / DMODEL);
    float var = q * (1.0f / DMODEL) - mu * mu;
    float r   = rsqrtf(var + 1e-5f);
    float2 gg = *(const float2*)&g[tid * 2];
    float2 bb = *(const float2*)&b[tid * 2];
    float ox = (v.x - mu) * r * gg.x + bb.x;
    float oy = (v.y - mu) * r * gg.y + bb.y;
    *(uint32_t*)&g_xnh[t * DMODEL + tid * 2] = hpack2(ox, oy);
}

// ---------------- fp16 split HMMA GEMM (PASSES = 1 or 2, OUTH fp16 out) ----------------
// C[m][n] = sum_k A[m][k]*B[n][k]; A fp16 hi (+lo if PASSES==2), B fp16 hi.
// PASSES==2: D = Ahi*Bhi + Alo*Bhi.  PASSES==1: D = Ahi*Bhi.
// OUTH: C is __half* (packed fp16 stores). 32 fp32-k per tile; rows padded
// to 40 halves. 8 warps 2(m) x 4(n). split-K via blockIdx.z.
// EPI: 0 none, 2 softplus(acc+ep[row]). NGUARD vs N.
template<int BM, int BN, int EPI, bool NGUARD, int PASSES, bool OUTH>
__global__ __launch_bounds__(256, 2)
void mma_gemm(const __half* __restrict__ Ah,
              const __half* __restrict__ Al, int lda,
              const __half* __restrict__ Bh, int ldb,
              void* __restrict__ Cv, int ldc,
              int M, int N, int K, const float* __restrict__ ep)
{
    constexpr int S = 40;
    constexpr int MT = (BM / 2) / 16;
    constexpr int NT = (BN / 4) / 8;
    constexpr int AIT = BM / 64;
    constexpr int BIT = BN / 64;
    constexpr int PERBUF = (PASSES * BM + BN) * S;

    extern __shared__ __align__(16) __half sm[];
    const uint32_t sb = smem_u32(sm);

    const int tid = threadIdx.x, lane = tid & 31, wid = tid >> 5;
    const int bm = blockIdx.y * BM, bn = blockIdx.x * BN;
    const int z = blockIdx.z;
    const int kbeg = z * K;
    float*  Cf = (float*)Cv  + (size_t)z * M * ldc;
    __half* Ch = (__half*)Cv + (size_t)z * M * ldc;
    const int wm0 = (wid & 1) * (BM / 2);
    const int wn0 = (wid >> 1) * (BN / 4);

    const int lA_r = lane & 15;
    const int lA_c = (lane >> 4) << 3;
    const int lB_r = (lane & 7) + ((lane >> 4) << 3);
    const int lB_c = ((lane >> 3) & 1) << 3;

    float acc[MT][NT][4];
    #pragma unroll
    for (int i = 0; i < MT; i++)
        #pragma unroll
        for (int j = 0; j < NT; j++)
            #pragma unroll
            for (int q = 0; q < 4; q++) acc[i][j][q] = 0.0f;

    uint4 vah[AIT], val[AIT], vbh[BIT];

    auto loadG = [&](int k0) {
        #pragma unroll
        for (int i = 0; i < AIT; i++) {
            int idx = tid + i * 256;
            int r = idx >> 2, ch = (idx & 3) << 3;
            size_t s = (size_t)(bm + r) * lda + k0 + ch;
            vah[i] = *(const uint4*)&Ah[s];
            if (PASSES == 2) val[i] = *(const uint4*)&Al[s];
        }
        #pragma unroll
        for (int i = 0; i < BIT; i++) {
            int idx = tid + i * 256;
            int r = idx >> 2, ch = (idx & 3) << 3;
            int rr = bn + r;
            if (NGUARD) rr = min(rr, N - 1);
            size_t s = (size_t)rr * ldb + k0 + ch;
            vbh[i] = *(const uint4*)&Bh[s];
        }
    };
    auto storeS = [&](int buf) {
        const int oAh = buf * PERBUF;
        const int oAl = oAh + BM * S;
        const int oBh = oAh + PASSES * BM * S;
        #pragma unroll
        for (int i = 0; i < AIT; i++) {
            int idx = tid + i * 256;
            int r = idx >> 2, ch = (idx & 3) << 3;
            *(uint4*)&sm[oAh + r * S + ch] = vah[i];
            if (PASSES == 2) *(uint4*)&sm[oAl + r * S + ch] = val[i];
        }
        #pragma unroll
        for (int i = 0; i < BIT; i++) {
            int idx = tid + i * 256;
            int r = idx >> 2, ch = (idx & 3) << 3;
            *(uint4*)&sm[oBh + r * S + ch] = vbh[i];
        }
    };
    auto compute = [&](int buf) {
        const int oAh = buf * PERBUF;
        const int oAl = oAh + BM * S;
        const int oBh = oAh + PASSES * BM * S;
        #pragma unroll
        for (int kk = 0; kk < 32; kk += 16) {
            uint32_t af[MT][4];
            uint32_t bh[NT / 2][4];
            #pragma unroll
            for (int mi = 0; mi < MT; mi++) {
                uint32_t addr = sb + (uint32_t)(oAh +
                    (wm0 + mi * 16 + lA_r) * S + kk + lA_c) * 2;
                ldsm4(af[mi][0], af[mi][1], af[mi][2], af[mi][3], addr);
            }
            #pragma unroll
            for (int nj = 0; nj < NT / 2; nj++) {
                uint32_t addr = sb + (uint32_t)(oBh +
                    (wn0 + nj * 16 + lB_r) * S + kk + lB_c) * 2;
                ldsm4(bh[nj][0], bh[nj][1], bh[nj][2], bh[nj][3], addr);
            }
            #pragma unroll
            for (int mi = 0; mi < MT; mi++)
                #pragma unroll
                for (int ni = 0; ni < NT; ni++)
                    mma_f16(acc[mi][ni],
                            af[mi][0], af[mi][1], af[mi][2], af[mi][3],
                            bh[ni >> 1][(ni & 1) * 2],
                            bh[ni >> 1][(ni & 1) * 2 + 1]);
            if (PASSES == 2) {
                #pragma unroll
                for (int mi = 0; mi < MT; mi++) {
                    uint32_t addr = sb + (uint32_t)(oAl +
                        (wm0 + mi * 16 + lA_r) * S + kk + lA_c) * 2;
                    ldsm4(af[mi][0], af[mi][1], af[mi][2], af[mi][3], addr);
                }
                #pragma unroll
                for (int mi = 0; mi < MT; mi++)
                    #pragma unroll
                    for (int ni = 0; ni < NT; ni++)
                        mma_f16(acc[mi][ni],
                                af[mi][0], af[mi][1], af[mi][2], af[mi][3],
                                bh[ni >> 1][(ni & 1) * 2],
                                bh[ni >> 1][(ni & 1) * 2 + 1]);
            }
        }
    };

    loadG(kbeg);
    storeS(0);
    __syncthreads();
    int cur = 0;
    const int KT = K / 32;
    for (int kt = 0; kt < KT; kt++) {
        bool has = (kt + 1) < KT;
        if (has) loadG(kbeg + (kt + 1) * 32);
        compute(cur);
        if (has) {
            storeS(cur ^ 1);
            __syncthreads();
            cur ^= 1;
        }
    }

    #pragma unroll
    for (int mi = 0; mi < MT; mi++) {
        #pragma unroll
        for (int ni = 0; ni < NT; ni++) {
            int colb = bn + wn0 + ni * 8;
            if (NGUARD && colb >= N) continue;
            int row = bm + wm0 + mi * 16 + (lane >> 2);
            int col = colb + (lane & 3) * 2;
            float2 v0 = make_float2(acc[mi][ni][0], acc[mi][ni][1]);
            float2 v1 = make_float2(acc[mi][ni][2], acc[mi][ni][3]);
            if (EPI == 2) {
                float b0 = ep[row], b1 = ep[row + 8];
                v0.x = softplusf(v0.x + b0); v0.y = softplusf(v0.y + b0);
                v1.x = softplusf(v1.x + b1); v1.y = softplusf(v1.y + b1);
            }
            if (OUTH) {
                *(uint32_t*)&Ch[(size_t)row * ldc + col] = hpack2(v0.x, v0.y);
                *(uint32_t*)&Ch[(size_t)(row + 8) * ldc + col] = hpack2(v1.x, v1.y);
            } else {
                *(float2*)&Cf[(size_t)row * ldc + col] = v0;
                *(float2*)&Cf[(size_t)(row + 8) * ldc + col] = v1;
            }
        }
    }
}

// reduce the 4 split-K partials (dbc) + fused dt fp16-hi emit
__global__ void reduce4_kernel()
{
    int i = (blockIdx.x * 256 + threadIdx.x) * 4;
    const int TOT = SEQ * DBCCOLS;
    float4 a = *(const float4*)&g_dbcp[0 * TOT + i];
    float4 b = *(const float4*)&g_dbcp[1 * TOT + i];
    float4 c = *(const float4*)&g_dbcp[2 * TOT + i];
    float4 d = *(const float4*)&g_dbcp[3 * TOT + i];
    float4 o;
    o.x = (a.x + b.x) + (c.x + d.x);
    o.y = (a.y + b.y) + (c.y + d.y);
    o.z = (a.z + b.z) + (c.z + d.z);
    o.w = (a.w + b.w) + (c.w + d.w);
    *(float4*)&g_dbc[i] = o;
    int t = i / DBCCOLS, cc = i % DBCCOLS;
    if (cc < DTRANK) {
        *(uint2*)&g_dth[t * DTRANK + cc] =
            make_uint2(hpack2(o.x, o.y), hpack2(o.z, o.w));
    }
}

// reduce 2 split-K partials of G4 and add residual -> final out
__global__ void reduce2_resid_kernel(const float* __restrict__ x,
                                     float* __restrict__ out)
{
    int i = (blockIdx.x * 256 + threadIdx.x) * 4;
    const int TOT = SEQ * DMODEL;
    float4 a = *(const float4*)&g_outp[i];
    float4 b = *(const float4*)&g_outp[TOT + i];
    float4 r = *(const float4*)&x[i];
    float4 o;
    o.x = a.x + b.x + r.x;
    o.y = a.y + b.y + r.y;
    o.z = a.z + b.z + r.z;
    o.w = a.w + b.w + r.w;
    *(float4*)&out[i] = o;
}

// ---------------- depthwise conv + silu (fp16 xz in): emits xi hi, xiT, zsT ----------------
__global__ __launch_bounds__(256)
void conv_kernel(const float* __restrict__ cw, const float* __restrict__ cb)
{
    __shared__ float sxz[35][33];
    __shared__ float sxi[32][33];
    __shared__ float szs[32][33];
    int t0 = blockIdx.x * 32, c0 = blockIdx.y * 32;
    int tid = threadIdx.x;

    for (int i = tid; i < 35 * 32; i += 256) {
        int r = i >> 5, c = i & 31;
        int gt = t0 + r - 3;
        sxz[r][c] = (gt >= 0)
            ? __half2float(g_xzh[(size_t)gt * XZCOLS + c0 + c]) : 0.0f;
    }
    for (int i = tid; i < 32 * 32; i += 256) {
        int r = i >> 5, c = i & 31;
        float z = __half2float(g_xzh[(size_t)(t0 + r) * XZCOLS + DINNER + c0 + c]);
        szs[r][c] = siluf(z);
    }
    __syncthreads();

    int cl = tid & 31, tq = tid >> 5;
    float4 w = *(const float4*)&cw[(c0 + cl) * 4];
    float bb = cb[c0 + cl];
    #pragma unroll
    for (int s = 0; s < 4; s++) {
        int tl = tq + s * 8;
        float v = sxz[tl + 0][cl] * w.x + sxz[tl + 1][cl] * w.y +
                  sxz[tl + 2][cl] * w.z + sxz[tl + 3][cl] * w.w + bb;
        v = siluf(v);
        g_xih[(size_t)(t0 + tl) * DINNER + c0 + cl] = __float2half_rn(v);
        sxi[tl][cl] = v;
    }
    __syncthreads();

    int tl2 = tid & 31, cq = tid >> 5;
    #pragma unroll
    for (int s = 0; s < 4; s++) {
        int cl2 = cq + s * 8;
        g_xiT[(size_t)(c0 + cl2) * SEQ + t0 + tl2] = sxi[tl2][cl2];
        g_zsT[(size_t)(c0 + cl2) * SEQ + t0 + tl2] = szs[tl2][cl2];
    }
}

// ---------------- chunked scan, pass 1 (chunks 0..NC-2 only) ----------------
__global__ __launch_bounds__(256)
void scan_pass1(const float* __restrict__ A_log)
{
    __shared__ __align__(16) float sB[32][68];
    const unsigned FULL = 0xffffffffu;
    int tid = threadIdx.x, lane = tid & 31, w = tid >> 5;
    int d = blockIdx.x * 8 + w;
    int c = blockIdx.y;

    float A0  = -expf(A_log[d * DSTATE + lane]);
    float A1  = -expf(A_log[d * DSTATE + 32 + lane]);
    float d32 = A1 - A0;
    bool uni  = __all_sync(FULL, __shfl_sync(FULL, d32, 0) == d32);
    float h0 = 0.f, h1 = 0.f, ssum = 0.f;

    const float* xT  = g_xiT + (size_t)d * SEQ;
    const float* dTp = g_dT  + (size_t)d * SEQ;
    const int tbeg = c * LC;

    for (int t0 = tbeg; t0 < tbeg + LC; t0 += 32) {
        __syncthreads();
        for (int i = tid; i < 32 * 16; i += 256) {
            int r = i >> 4, q = (i & 15) << 2;
            *(float4*)&sB[r][q] =
                *(const float4*)&g_dbc[(size_t)(t0 + r) * DBCCOLS + 32 + q];
        }
        __syncthreads();

        float myD   = dTp[t0 + lane];
        float myDux = myD * xT[t0 + lane];
        float myE32 = __expf(myD * d32);
        ssum += myD;

        #pragma unroll 8
        for (int i = 0; i < 32; i++) {
            float du  = __shfl_sync(FULL, myD,   i);
            float dux = __shfl_sync(FULL, myDux, i);
            float e0  = __expf(du * A0);
            float e1  = uni ? e0 * __shfl_sync(FULL, myE32, i)
                            : __expf(du * A1);
            h0 = fmaf(e0, h0, dux * sB[i][lane]);
            h1 = fmaf(e1, h1, dux * sB[i][32 + lane]);
        }
    }
    float S = ssum;
    #pragma unroll
    for (int o = 16; o > 0; o >>= 1) S += __shfl_xor_sync(FULL, S, o);
    if (lane == 0) g_S[d * NC + c] = S;
    float* he = g_hend + ((size_t)c * DINNER + d) * DSTATE;
    he[lane] = h0;
    he[32 + lane] = h1;
}

// ---------------- pass 3: y scan with inline chunk-chain init + fp16 out ----------------
__global__ __launch_bounds__(256)
void scan_pass3(const float* __restrict__ A_log, const float* __restrict__ Dp)
{
    __shared__ __align__(16) float sD[32][132];
    __shared__ float sY[32][9];
    const unsigned FULL = 0xffffffffu;
    int tid = threadIdx.x, lane = tid & 31, w = tid >> 5;
    int d0 = blockIdx.x * 8;
    int d = d0 + w;
    int c = blockIdx.y;

    float A0  = -expf(A_log[d * DSTATE + lane]);
    float A1  = -expf(A_log[d * DSTATE + 32 + lane]);
    float d32 = A1 - A0;
    bool uni  = __all_sync(FULL, __shfl_sync(FULL, d32, 0) == d32);
    float Dpd = Dp[d];

    // inline pass2: chain chunks 0..c-1
    float h0 = 0.f, h1 = 0.f;
    for (int cc = 0; cc < c; cc++) {
        float Sv = g_S[d * NC + cc];
        float E0 = __expf(A0 * Sv);
        float E1 = __expf(A1 * Sv);
        const float* he = g_hend + ((size_t)cc * DINNER + d) * DSTATE;
        h0 = fmaf(E0, h0, he[lane]);
        h1 = fmaf(E1, h1, he[32 + lane]);
    }

    const float* xT  = g_xiT + (size_t)d * SEQ;
    const float* zT  = g_zsT + (size_t)d * SEQ;
    const float* dTp = g_dT  + (size_t)d * SEQ;
    const int tbeg = c * LC;

    const int ot = tid >> 3, od = tid & 7;

    for (int t0 = tbeg; t0 < tbeg + LC; t0 += 32) {
        __syncthreads();
        for (int i = tid; i < 32 * 32; i += 256) {
            int r = i >> 5, q = (i & 31) << 2;
            *(float4*)&sD[r][q] =
                *(const float4*)&g_dbc[(size_t)(t0 + r) * DBCCOLS + 32 + q];
        }
        __syncthreads();

        float myD   = dTp[t0 + lane];
        float myX   = xT[t0 + lane];
        float myZ   = zT[t0 + lane];
        float myDux = myD * myX;
        float myE32 = __expf(myD * d32);

        float p[32];
        #pragma unroll
        for (int i = 0; i < 32; i++) {
            float du  = __shfl_sync(FULL, myD,   i);
            float dux = __shfl_sync(FULL, myDux, i);
            float e0  = __expf(du * A0);
            float e1  = uni ? e0 * __shfl_sync(FULL, myE32, i)
                            : __expf(du * A1);
            h0 = fmaf(e0, h0, dux * sD[i][lane]);
            h1 = fmaf(e1, h1, dux * sD[i][32 + lane]);
            p[i] = fmaf(h0, sD[i][64 + lane], h1 * sD[i][96 + lane]);
        }

        #pragma unroll
        for (int o = 16; o >= 1; o >>= 1) {
            bool hi = (lane & o) != 0;
            #pragma unroll
            for (int jj = 0; jj < o; jj++) {
                float keep = hi ? p[o + jj] : p[jj];
                float send = hi ? p[jj] : p[o + jj];
                p[jj] = keep + __shfl_xor_sync(FULL, send, o);
            }
        }

        sY[lane][w] = (p[0] + Dpd * myX) * myZ;
        __syncthreads();

        float v = sY[ot][od];
        g_yh[(size_t)(t0 + ot) * DINNER + d0 + od] = __float2half_rn(v);
    }
}

// ---------------- launcher ----------------
extern "C" void kernel_launch(void* const* d_in, const int* in_sizes, int n_in,
                              void* d_out, int out_size)
{
    const float* x      = (const float*)d_in[0];
    const float* ln_g   = (const float*)d_in[1];
    const float* ln_b   = (const float*)d_in[2];
    const float* Win    = (const float*)d_in[3];
    const float* conv_w = (const float*)d_in[4];
    const float* conv_b = (const float*)d_in[5];
    const float* Wx     = (const float*)d_in[6];
    const float* Wdt    = (const float*)d_in[7];
    const float* bdt    = (const float*)d_in[8];
    const float* A_log  = (const float*)d_in[9];
    const float* Dp     = (const float*)d_in[10];
    const float* Wout   = (const float*)d_in[11];
    float* out = (float*)d_out;

    float *p_dbcp, *p_dT, *p_outp;
    cudaGetSymbolAddress((void**)&p_dbcp, g_dbcp);
    cudaGetSymbolAddress((void**)&p_dT,   g_dT);
    cudaGetSymbolAddress((void**)&p_outp, g_outp);
    __half *p_xzh, *p_xnh, *p_Winh, *p_xih, *p_Wxh;
    __half *p_dth, *p_Wdth, *p_Wdtl, *p_yh, *p_Wouth;
    cudaGetSymbolAddress((void**)&p_xzh,   g_xzh);
    cudaGetSymbolAddress((void**)&p_xnh,   g_xnh);
    cudaGetSymbolAddress((void**)&p_Winh,  g_Winh);
    cudaGetSymbolAddress((void**)&p_xih,   g_xih);
    cudaGetSymbolAddress((void**)&p_Wxh,   g_Wxh);
    cudaGetSymbolAddress((void**)&p_dth,   g_dth);
    cudaGetSymbolAddress((void**)&p_Wdth,  g_Wdth);
    cudaGetSymbolAddress((void**)&p_Wdtl,  g_Wdtl);
    cudaGetSymbolAddress((void**)&p_yh,    g_yh);
    cudaGetSymbolAddress((void**)&p_Wouth, g_Wouth);

    // dynamic smem: (PASSES*BM + BN) * 40 halves * 2B * 2 bufs
    const int smem_1p_128 = (1 * 128 + 128) * 40 * 2 * 2;  // 40960
    const int smem_1p_64  = (1 * 128 + 64) * 40 * 2 * 2;   // 30720
    const int smem_2p_128 = (2 * 128 + 128) * 40 * 2 * 2;  // 61440
    cudaFuncSetAttribute(mma_gemm<128, 128, 0, false, 1, true>,
        cudaFuncAttributeMaxDynamicSharedMemorySize, smem_1p_128);
    cudaFuncSetAttribute(mma_gemm<128, 64, 0, true, 1, false>,
        cudaFuncAttributeMaxDynamicSharedMemorySize, smem_1p_64);
    cudaFuncSetAttribute(mma_gemm<128, 128, 2, false, 2, false>,
        cudaFuncAttributeMaxDynamicSharedMemorySize, smem_2p_128);
    cudaFuncSetAttribute(mma_gemm<128, 64, 0, false, 1, false>,
        cudaFuncAttributeMaxDynamicSharedMemorySize, smem_1p_64);

    // 0. split all weights (one launch)
    split_all_kernel<<<1728, 256>>>(Win, Wx, Wdt, Wout);

    // 1. LayerNorm -> xn hi
    ln_kernel<<<SEQ, 256>>>(x, ln_g, ln_b);

    // 2. xz = xn @ Win^T  [2048 x 2048 x 512]  1-pass fp16, fp16 output
    mma_gemm<128, 128, 0, false, 1, true><<<dim3(16, 16), 256, smem_1p_128>>>(
        p_xnh, nullptr, DMODEL, p_Winh, DMODEL,
        p_xzh, XZCOLS, SEQ, XZCOLS, DMODEL, nullptr);

    // 3. conv + silu (fp16 in) -> xi hi, xiT, zsT
    conv_kernel<<<dim3(SEQ / 32, DINNER / 32), 256>>>(conv_w, conv_b);

    // 4. dbc = xi @ Wx^T  [2048 x 160 x 1024]  1-pass, split-K=4 + fused reduce
    mma_gemm<128, 64, 0, true, 1, false><<<dim3(3, 16, NSPLIT), 256, smem_1p_64>>>(
        p_xih, nullptr, DINNER, p_Wxh, DINNER,
        p_dbcp, DBCCOLS, SEQ, DBCCOLS, DINNER / NSPLIT, nullptr);
    reduce4_kernel<<<SEQ * DBCCOLS / 1024, 256>>>();

    // 5. delta^T = softplus(Wdt @ dt^T + bdt)  [1024 x 2048 x 32]  2-pass
    mma_gemm<128, 128, 2, false, 2, false><<<dim3(16, 8), 256, smem_2p_128>>>(
        p_Wdth, p_Wdtl, DTRANK, p_dth, DTRANK,
        p_dT, SEQ, DINNER, SEQ, DTRANK, bdt);

    // 6. chunked selective scan: pass1 (chunks 0..NC-2) then pass3 with
    //    inline chunk-chain init; pass3 emits y fp16 [t][d] directly
    scan_pass1<<<dim3(DINNER / 8, NC - 1), 256>>>(A_log);
    scan_pass3<<<dim3(DINNER / 8, NC), 256>>>(A_log, Dp);

    // 7. out = y @ Wout^T  [2048 x 512 x 1024]  1-pass fp16, split-K=2, +resid
    mma_gemm<128, 64, 0, false, 1, false><<<dim3(8, 16, G4SPLIT), 256, smem_1p_64>>>(
        p_yh, nullptr, DINNER, p_Wouth, DINNER,
        p_outp, DMODEL, SEQ, DMODEL, DINNER / G4SPLIT, nullptr);
    reduce2_resid_kernel<<<SEQ * DMODEL / 1024, 256>>>(x, out);
}